// round 4
// baseline (speedup 1.0000x reference)
#include <cuda_runtime.h>
#include <cuda_bf16.h>

// ---------------------------------------------------------------------------
// GraphSAGE(pool) x3 + BN + classifier — GB300 sm_103a
// Round 4: HMMA bf16-split GEMM with (a) W as pre-packed register fragments
// loaded via LDG (no smem staging), (b) activations stored as bf16 hi/lo so
// A-staging is pure cp.async, (c) 68KB smem -> 2 CTAs/SM for overlap.
// ---------------------------------------------------------------------------

#define NNODES 100000
#define NEDGES 1000000
#define F      128
#define NCLS   16
#define NEG_SLOPE 0.01f
#define BN_EPS    1e-5f
#define TILE_M 128
#define NTILES ((NNODES + TILE_M - 1) / TILE_M)   // 782

#define ACT_NONE  0
#define ACT_RELU  1
#define ACT_LEAKY 2

typedef unsigned int u32;
typedef unsigned long long u64;

// ------------------------------ scratch -----------------------------------
__device__ __align__(256) float g_hp [(size_t)NNODES * F];          // fp32 (agg gather input)
__device__ __align__(256) __nv_bfloat16 g_xh [(size_t)NNODES * F];
__device__ __align__(256) __nv_bfloat16 g_xl [(size_t)NNODES * F];
__device__ __align__(256) __nv_bfloat16 g_agh[(size_t)NNODES * F];
__device__ __align__(256) __nv_bfloat16 g_agl[(size_t)NNODES * F];
__device__ __align__(256) __nv_bfloat16 g_h1h[(size_t)NNODES * F];
__device__ __align__(256) __nv_bfloat16 g_h1l[(size_t)NNODES * F];
__device__ __align__(256) __nv_bfloat16 g_h2h[(size_t)NNODES * F];
__device__ __align__(256) __nv_bfloat16 g_h2l[(size_t)NNODES * F];
__device__ __align__(256) uint2 g_wfh[9 * 4096];   // B fragments hi: [w][k16][n8][lane]
__device__ __align__(256) uint2 g_wfl[9 * 4096];   // B fragments lo
__device__ int   g_deg[NNODES];
__device__ int   g_rowptr[NNODES + 1];
__device__ int   g_cursor[NNODES];
__device__ int   g_col[NEDGES];
__device__ float g_sums[2 * F];

// ------------------------------ helpers -----------------------------------
__device__ __forceinline__ u32 smem_u32(const void* p) {
    u32 a;
    asm("{ .reg .u64 t; cvta.to.shared.u64 t, %1; cvt.u32.u64 %0, t; }"
        : "=r"(a) : "l"(p));
    return a;
}

__device__ __forceinline__ float bfh(u32 w) { return __uint_as_float(w & 0xffff0000u); }
__device__ __forceinline__ float bfl(u32 w) { return __uint_as_float(w << 16); }

__device__ __forceinline__ void split_pair(float a, float b, u32& oh, u32& ol) {
    __nv_bfloat16 ha = __float2bfloat16(a), hb = __float2bfloat16(b);
    __nv_bfloat16 la = __float2bfloat16(a - __bfloat162float(ha));
    __nv_bfloat16 lb = __float2bfloat16(b - __bfloat162float(hb));
    oh = (u32)__bfloat16_as_ushort(ha) | ((u32)__bfloat16_as_ushort(hb) << 16);
    ol = (u32)__bfloat16_as_ushort(la) | ((u32)__bfloat16_as_ushort(lb) << 16);
}

__device__ __forceinline__ void ldm_x4(u32 addr, u32& r0, u32& r1, u32& r2, u32& r3) {
    asm volatile("ldmatrix.sync.aligned.m8n8.x4.shared.b16 {%0,%1,%2,%3}, [%4];"
                 : "=r"(r0), "=r"(r1), "=r"(r2), "=r"(r3) : "r"(addr));
}

__device__ __forceinline__ void mma16816(float* c, const u32* a, u32 b0, u32 b1) {
    asm volatile("mma.sync.aligned.m16n8k16.row.col.f32.bf16.bf16.f32 "
                 "{%0,%1,%2,%3}, {%4,%5,%6,%7}, {%8,%9}, {%0,%1,%2,%3};"
                 : "+f"(c[0]), "+f"(c[1]), "+f"(c[2]), "+f"(c[3])
                 : "r"(a[0]), "r"(a[1]), "r"(a[2]), "r"(a[3]), "r"(b0), "r"(b1));
}

__device__ __forceinline__ void cp16(u32 dst, const void* src, int sz) {
    asm volatile("cp.async.cg.shared.global [%0], [%1], 16, %2;"
                 :: "r"(dst), "l"(__cvta_generic_to_global(src)), "r"(sz) : "memory");
}

// ------------------------------ CSR build ---------------------------------
__global__ void zero_prep() {
    int i = blockIdx.x * blockDim.x + threadIdx.x;
    if (i < NNODES) g_deg[i] = 0;
    if (i < 2 * F)  g_sums[i] = 0.f;
}

__global__ void deg_kernel(const int* __restrict__ dst) {
    int i = blockIdx.x * blockDim.x + threadIdx.x;
    if (i < NEDGES) atomicAdd(&g_deg[dst[i]], 1);
}

__global__ void scan_kernel() {
    __shared__ int sh[1024];
    int t = threadIdx.x;
    const int chunk = (NNODES + 1023) / 1024;
    int beg = t * chunk; if (beg > NNODES) beg = NNODES;
    int end = beg + chunk; if (end > NNODES) end = NNODES;
    int s = 0;
    for (int i = beg; i < end; i++) s += g_deg[i];
    sh[t] = s;
    __syncthreads();
    for (int off = 1; off < 1024; off <<= 1) {
        int v = (t >= off) ? sh[t - off] : 0;
        __syncthreads();
        sh[t] += v;
        __syncthreads();
    }
    int run = (t == 0) ? 0 : sh[t - 1];
    for (int i = beg; i < end; i++) {
        g_rowptr[i] = run;
        g_cursor[i] = run;
        run += g_deg[i];
    }
    if (t == 1023) g_rowptr[NNODES] = sh[1023];
}

__global__ void fill_kernel(const int* __restrict__ src,
                            const int* __restrict__ dst) {
    int i = blockIdx.x * blockDim.x + threadIdx.x;
    if (i < NEDGES) {
        int p = atomicAdd(&g_cursor[dst[i]], 1);
        g_col[p] = src[i];
    }
}

// ------------------------------ packing -----------------------------------
__global__ void pack_x(const float* __restrict__ x,
                       __nv_bfloat16* __restrict__ xh,
                       __nv_bfloat16* __restrict__ xl) {
    size_t i = (size_t)blockIdx.x * blockDim.x + threadIdx.x;
    size_t total = (size_t)NNODES * F / 4;
    if (i >= total) return;
    float4 v = ((const float4*)x)[i];
    uint2 oh, ol;
    split_pair(v.x, v.y, oh.x, ol.x);
    split_pair(v.z, v.w, oh.y, ol.y);
    ((uint2*)xh)[i] = oh;
    ((uint2*)xl)[i] = ol;
}

// W [K=128, N=128] fp32 -> mma.m16n8k16 B fragments (hi/lo split).
// frag index t = (k16*16 + n8)*32 + lane; thread holds b0 = W[kb..kb+1, n],
// b1 = W[kb+8..kb+9, n] with n = n8*8 + lane/4, kb = k16*16 + (lane%4)*2.
__global__ void pack_wfrag(const float* __restrict__ W,
                           uint2* __restrict__ fh, uint2* __restrict__ fl) {
    int t = blockIdx.x * blockDim.x + threadIdx.x;
    if (t >= 4096) return;
    int lane = t & 31, n8 = (t >> 5) & 15, k16 = t >> 9;
    int n  = n8 * 8 + (lane >> 2);
    int kb = k16 * 16 + (lane & 3) * 2;
    float v00 = W[kb * F + n],       v01 = W[(kb + 1) * F + n];
    float v10 = W[(kb + 8) * F + n], v11 = W[(kb + 9) * F + n];
    u32 h0, l0, h1, l1;
    split_pair(v00, v01, h0, l0);
    split_pair(v10, v11, h1, l1);
    fh[t] = make_uint2(h0, h1);
    fl[t] = make_uint2(l0, l1);
}

// ---------------------- segment-max aggregation ----------------------------
// fp32 gather (hp), split bf16 output (agg feeds MMA). hp >= 0 post-relu.
__global__ void __launch_bounds__(256) agg_max(const float* __restrict__ hp,
                                               __nv_bfloat16* __restrict__ Oh,
                                               __nv_bfloat16* __restrict__ Ol) {
    int node = (blockIdx.x * blockDim.x + threadIdx.x) >> 5;
    int lane = threadIdx.x & 31;
    if (node >= NNODES) return;
    int beg = g_rowptr[node];
    int end = g_rowptr[node + 1];
    float4 acc = make_float4(0.f, 0.f, 0.f, 0.f);
    const float4* hp4 = (const float4*)hp;
    for (int base = beg; base < end; base += 32) {
        int m = end - base; if (m > 32) m = 32;
        int idx = (lane < m) ? g_col[base + lane] : 0;
        for (int j = 0; j < m; j++) {
            int s = __shfl_sync(0xffffffffu, idx, j);
            float4 v = hp4[(size_t)s * 32 + lane];
            acc.x = fmaxf(acc.x, v.x);
            acc.y = fmaxf(acc.y, v.y);
            acc.z = fmaxf(acc.z, v.z);
            acc.w = fmaxf(acc.w, v.w);
        }
    }
    uint2 oh, ol;
    split_pair(acc.x, acc.y, oh.x, ol.x);
    split_pair(acc.z, acc.w, oh.y, ol.y);
    ((uint2*)(Oh + (size_t)node * F))[lane] = oh;
    ((uint2*)(Ol + (size_t)node * F))[lane] = ol;
}

// ------------------------------- HMMA GEMM ---------------------------------
// C[nRows,128] = A@W (+ A2@W2) + bias (+act). A: bf16 hi/lo arrays, staged via
// cp.async into smem (272B row stride). W: pre-packed fragments via LDG.
#define RSTRIDE 272
#define TBYTES (128 * RSTRIDE)   // 34816

__global__ void __launch_bounds__(256, 2) mma_gemm(
    const __nv_bfloat16* __restrict__ Ah, const __nv_bfloat16* __restrict__ Al,
    const uint2* __restrict__ WFh, const uint2* __restrict__ WFl,
    const __nv_bfloat16* __restrict__ A2h, const __nv_bfloat16* __restrict__ A2l,
    const uint2* __restrict__ WF2h, const uint2* __restrict__ WF2l,
    const float* __restrict__ bias,
    float* __restrict__ Cf,                       // fp32 output (or null)
    __nv_bfloat16* __restrict__ Ch, __nv_bfloat16* __restrict__ Cl,  // split output
    int nRows, int act)
{
    extern __shared__ char dyn[];
    __shared__ float s_bias[F];
    u32 base = smem_u32(dyn);
    const u32 AH = base, AL = base + TBYTES;

    int tid  = threadIdx.x;
    int wid  = tid >> 5;
    int lane = tid & 31;
    int warp_m = wid & 3;
    int warp_n = wid >> 2;
    int row0 = blockIdx.x * TILE_M;

    if (tid < F) s_bias[tid] = bias[tid];

    float acc[2][8][4];
    #pragma unroll
    for (int mt = 0; mt < 2; mt++)
        #pragma unroll
        for (int nt = 0; nt < 8; nt++)
            #pragma unroll
            for (int q = 0; q < 4; q++) acc[mt][nt][q] = 0.f;

    u32 a_row  = (u32)(warp_m * 32) + (lane & 15);
    u32 a_koff = (u32)(lane >> 4) * 16;
    u32 fbase  = (u32)(warp_n * 8) * 32 + lane;

    int nPass = (A2h != nullptr) ? 2 : 1;
    for (int pass = 0; pass < nPass; pass++) {
        const __nv_bfloat16* ah_g = pass ? A2h : Ah;
        const __nv_bfloat16* al_g = pass ? A2l : Al;
        const uint2* wfh = pass ? WF2h : WFh;
        const uint2* wfl = pass ? WF2l : WFl;

        if (pass) __syncthreads();   // previous tiles fully consumed

        // stage A hi/lo via cp.async (16B granules, zero-fill OOB rows)
        #pragma unroll
        for (int i = 0; i < 8; i++) {
            int g = tid + i * 256;       // 0..2047
            int r = g >> 4;
            int j = g & 15;
            int gr = row0 + r;
            int ok = (gr < nRows);
            size_t srcoff = ((size_t)(ok ? gr : 0) * F + (j << 3));
            u32 off = (u32)r * RSTRIDE + (u32)j * 16;
            cp16(AH + off, ah_g + srcoff, ok ? 16 : 0);
            cp16(AL + off, al_g + srcoff, ok ? 16 : 0);
        }
        asm volatile("cp.async.commit_group;" ::: "memory");
        asm volatile("cp.async.wait_group 0;" ::: "memory");
        __syncthreads();

        #pragma unroll
        for (int k16 = 0; k16 < 8; k16++) {
            u32 kbase = (u32)k16 * 32;
            u32 ah[2][4], al[2][4];
            #pragma unroll
            for (int mt = 0; mt < 2; mt++) {
                u32 off = (a_row + mt * 16) * RSTRIDE + kbase + a_koff;
                ldm_x4(AH + off, ah[mt][0], ah[mt][1], ah[mt][2], ah[mt][3]);
                ldm_x4(AL + off, al[mt][0], al[mt][1], al[mt][2], al[mt][3]);
            }
            const uint2* ph = wfh + (size_t)(k16 * 16) * 32 + fbase;
            const uint2* pl = wfl + (size_t)(k16 * 16) * 32 + fbase;
            #pragma unroll
            for (int nt = 0; nt < 8; nt++) {
                uint2 bh = ph[nt * 32];
                uint2 bl = pl[nt * 32];
                mma16816(acc[0][nt], ah[0], bh.x, bh.y);
                mma16816(acc[0][nt], ah[0], bl.x, bl.y);
                mma16816(acc[0][nt], al[0], bh.x, bh.y);
                mma16816(acc[1][nt], ah[1], bh.x, bh.y);
                mma16816(acc[1][nt], ah[1], bl.x, bl.y);
                mma16816(acc[1][nt], al[1], bh.x, bh.y);
            }
        }
    }

    // epilogue
    int rbase = row0 + warp_m * 32 + (lane >> 2);
    int cbase = warp_n * 64 + (lane & 3) * 2;
    #pragma unroll
    for (int mt = 0; mt < 2; mt++) {
        #pragma unroll
        for (int half = 0; half < 2; half++) {
            int grow = rbase + mt * 16 + half * 8;
            if (grow >= nRows) continue;
            #pragma unroll
            for (int nt = 0; nt < 8; nt++) {
                int col = cbase + nt * 8;
                float v0 = acc[mt][nt][2 * half]     + s_bias[col];
                float v1 = acc[mt][nt][2 * half + 1] + s_bias[col + 1];
                if (act == ACT_RELU) {
                    v0 = fmaxf(v0, 0.f); v1 = fmaxf(v1, 0.f);
                } else if (act == ACT_LEAKY) {
                    v0 = (v0 > 0.f) ? v0 : v0 * NEG_SLOPE;
                    v1 = (v1 > 0.f) ? v1 : v1 * NEG_SLOPE;
                }
                if (Cf) {
                    *(float2*)&Cf[(size_t)grow * F + col] = make_float2(v0, v1);
                } else {
                    u32 oh, ol;
                    split_pair(v0, v1, oh, ol);
                    ((u32*)Ch)[((size_t)grow * F + col) >> 1] = oh;
                    ((u32*)Cl)[((size_t)grow * F + col) >> 1] = ol;
                }
            }
        }
    }
}

// ------------------------------ BatchNorm ----------------------------------
__global__ void bn_stats(const __nv_bfloat16* __restrict__ Xh,
                         const __nv_bfloat16* __restrict__ Xl) {
    int cp   = threadIdx.x & 63;    // column pair (cols 2cp, 2cp+1)
    int half = threadIdx.x >> 6;    // 0..3
    float s0 = 0.f, s1 = 0.f, q0 = 0.f, q1 = 0.f;
    for (int r = blockIdx.x * 4 + half; r < NNODES; r += gridDim.x * 4) {
        u32 h = ((const u32*)(Xh + (size_t)r * F))[cp];
        u32 l = ((const u32*)(Xl + (size_t)r * F))[cp];
        float v0 = bfl(h) + bfl(l);
        float v1 = bfh(h) + bfh(l);
        s0 += v0; q0 += v0 * v0;
        s1 += v1; q1 += v1 * v1;
    }
    __shared__ float sh0[256], sh1[256], sq0[256], sq1[256];
    sh0[threadIdx.x] = s0; sh1[threadIdx.x] = s1;
    sq0[threadIdx.x] = q0; sq1[threadIdx.x] = q1;
    __syncthreads();
    if (half == 0) {
        s0 = sh0[cp] + sh0[cp + 64] + sh0[cp + 128] + sh0[cp + 192];
        s1 = sh1[cp] + sh1[cp + 64] + sh1[cp + 128] + sh1[cp + 192];
        q0 = sq0[cp] + sq0[cp + 64] + sq0[cp + 128] + sq0[cp + 192];
        q1 = sq1[cp] + sq1[cp + 64] + sq1[cp + 128] + sq1[cp + 192];
        atomicAdd(&g_sums[2 * cp],         s0);
        atomicAdd(&g_sums[2 * cp + 1],     s1);
        atomicAdd(&g_sums[F + 2 * cp],     q0);
        atomicAdd(&g_sums[F + 2 * cp + 1], q1);
    }
}

__global__ void bn_apply_leaky(__nv_bfloat16* __restrict__ Xh,
                               __nv_bfloat16* __restrict__ Xl,
                               const float* __restrict__ gamma,
                               const float* __restrict__ beta) {
    __shared__ float scale[F], shift[F];
    if (threadIdx.x < F) {
        float mu  = g_sums[threadIdx.x] * (1.f / NNODES);
        float var = g_sums[F + threadIdx.x] * (1.f / NNODES) - mu * mu;
        float sc  = rsqrtf(var + BN_EPS) * gamma[threadIdx.x];
        scale[threadIdx.x] = sc;
        shift[threadIdx.x] = beta[threadIdx.x] - mu * sc;
    }
    __syncthreads();
    size_t total = (size_t)NNODES * 16;   // 8-element groups
    for (size_t i = blockIdx.x * blockDim.x + threadIdx.x; i < total;
         i += (size_t)gridDim.x * blockDim.x) {
        int c = (int)(i & 15) * 8;
        uint4 hv = ((uint4*)Xh)[i];
        uint4 lv = ((uint4*)Xl)[i];
        u32 ha[4] = {hv.x, hv.y, hv.z, hv.w};
        u32 la[4] = {lv.x, lv.y, lv.z, lv.w};
        u32 oh[4], ol[4];
        #pragma unroll
        for (int w = 0; w < 4; w++) {
            float v0 = bfl(ha[w]) + bfl(la[w]);
            float v1 = bfh(ha[w]) + bfh(la[w]);
            v0 = v0 * scale[c + 2*w]     + shift[c + 2*w];
            v1 = v1 * scale[c + 2*w + 1] + shift[c + 2*w + 1];
            v0 = (v0 > 0.f) ? v0 : v0 * NEG_SLOPE;
            v1 = (v1 > 0.f) ? v1 : v1 * NEG_SLOPE;
            split_pair(v0, v1, oh[w], ol[w]);
        }
        ((uint4*)Xh)[i] = make_uint4(oh[0], oh[1], oh[2], oh[3]);
        ((uint4*)Xl)[i] = make_uint4(ol[0], ol[1], ol[2], ol[3]);
    }
}

// ------------------------------ classifier ---------------------------------
__global__ void classifier(const __nv_bfloat16* __restrict__ Hh,
                           const __nv_bfloat16* __restrict__ Hl,
                           const float* __restrict__ wc,
                           const float* __restrict__ bc,
                           float* __restrict__ out) {
    __shared__ float w[F * NCLS];
    __shared__ float b[NCLS];
    for (int i = threadIdx.x; i < F * NCLS; i += blockDim.x) w[i] = wc[i];
    if (threadIdx.x < NCLS) b[threadIdx.x] = bc[threadIdx.x];
    __syncthreads();
    int r = blockIdx.x * blockDim.x + threadIdx.x;
    if (r >= NNODES) return;
    float acc[NCLS];
    #pragma unroll
    for (int j = 0; j < NCLS; j++) acc[j] = 0.f;
    for (int k = 0; k < F; k += 8) {
        uint4 hv = *(const uint4*)(Hh + (size_t)r * F + k);
        uint4 lv = *(const uint4*)(Hl + (size_t)r * F + k);
        u32 ha[4] = {hv.x, hv.y, hv.z, hv.w};
        u32 la[4] = {lv.x, lv.y, lv.z, lv.w};
        #pragma unroll
        for (int t = 0; t < 4; t++) {
            float f0 = bfl(ha[t]) + bfl(la[t]);
            float f1 = bfh(ha[t]) + bfh(la[t]);
            #pragma unroll
            for (int j = 0; j < NCLS; j++)
                acc[j] += f0 * w[(k + 2*t) * NCLS + j] + f1 * w[(k + 2*t + 1) * NCLS + j];
        }
    }
    #pragma unroll
    for (int j = 0; j < NCLS; j++)
        out[(size_t)r * NCLS + j] = acc[j] + b[j];
}

// ------------------------------ launch -------------------------------------
extern "C" void kernel_launch(void* const* d_in, const int* in_sizes, int n_in,
                              void* d_out, int out_size) {
    const float* x   = (const float*)d_in[0];
    const int*   src = (const int*)  d_in[1];
    const int*   dst = (const int*)  d_in[2];
    const float* wp[3] = { (const float*)d_in[3], (const float*)d_in[8],  (const float*)d_in[13] };
    const float* bp[3] = { (const float*)d_in[4], (const float*)d_in[9],  (const float*)d_in[14] };
    const float* ws[3] = { (const float*)d_in[5], (const float*)d_in[10], (const float*)d_in[15] };
    const float* wn[3] = { (const float*)d_in[6], (const float*)d_in[11], (const float*)d_in[16] };
    const float* bb[3] = { (const float*)d_in[7], (const float*)d_in[12], (const float*)d_in[17] };
    const float* gam = (const float*)d_in[18];
    const float* bet = (const float*)d_in[19];
    const float* wc  = (const float*)d_in[20];
    const float* bc  = (const float*)d_in[21];
    float* out = (float*)d_out;

    float* hp;
    __nv_bfloat16 *xh, *xl, *agh, *agl, *h1h, *h1l, *h2h, *h2l;
    uint2 *wfh, *wfl;
    cudaGetSymbolAddress((void**)&hp,  g_hp);
    cudaGetSymbolAddress((void**)&xh,  g_xh);
    cudaGetSymbolAddress((void**)&xl,  g_xl);
    cudaGetSymbolAddress((void**)&agh, g_agh);
    cudaGetSymbolAddress((void**)&agl, g_agl);
    cudaGetSymbolAddress((void**)&h1h, g_h1h);
    cudaGetSymbolAddress((void**)&h1l, g_h1l);
    cudaGetSymbolAddress((void**)&h2h, g_h2h);
    cudaGetSymbolAddress((void**)&h2l, g_h2l);
    cudaGetSymbolAddress((void**)&wfh, g_wfh);
    cudaGetSymbolAddress((void**)&wfl, g_wfl);

    const int SMEM_DYN = 2 * TBYTES;   // 69632
    cudaFuncSetAttribute(mma_gemm, cudaFuncAttributeMaxDynamicSharedMemorySize, SMEM_DYN);

    const int edgeGrid = (NEDGES + 255) / 256;
    const int aggGrid  = (NNODES * 32 + 255) / 256;

    // CSR build
    zero_prep<<<(NNODES + 255) / 256, 256>>>();
    deg_kernel<<<edgeGrid, 256>>>(dst);
    scan_kernel<<<1, 1024>>>();
    fill_kernel<<<edgeGrid, 256>>>(src, dst);

    // pack inputs + weight fragments (slot 3i=wp, 3i+1=ws, 3i+2=wn)
    pack_x<<<(NNODES * F / 4 + 255) / 256, 256>>>(x, xh, xl);
    for (int i = 0; i < 3; i++) {
        pack_wfrag<<<16, 256>>>(wp[i], wfh + (3*i)     * 4096, wfl + (3*i)     * 4096);
        pack_wfrag<<<16, 256>>>(ws[i], wfh + (3*i + 1) * 4096, wfl + (3*i + 1) * 4096);
        pack_wfrag<<<16, 256>>>(wn[i], wfh + (3*i + 2) * 4096, wfl + (3*i + 2) * 4096);
    }

    const __nv_bfloat16 *hinh = xh, *hinl = xl;
    __nv_bfloat16* houth[3] = { h1h, h2h, h1h };
    __nv_bfloat16* houtl[3] = { h1l, h2l, h1l };
    int actOut[3] = { ACT_LEAKY, ACT_NONE, ACT_NONE };

    for (int i = 0; i < 3; i++) {
        // hp = relu(h @ wp + bp)   (fp32 out for agg gather)
        mma_gemm<<<NTILES, 256, SMEM_DYN>>>(
            hinh, hinl, wfh + (3*i) * 4096, wfl + (3*i) * 4096,
            nullptr, nullptr, nullptr, nullptr,
            bp[i], hp, nullptr, nullptr, NNODES, ACT_RELU);
        // agg = segment_max(hp[src] -> dst)  (split out)
        agg_max<<<aggGrid, 256>>>(hp, agh, agl);
        // h' = h @ ws + agg @ wn + b  (split out)
        mma_gemm<<<NTILES, 256, SMEM_DYN>>>(
            hinh, hinl, wfh + (3*i + 1) * 4096, wfl + (3*i + 1) * 4096,
            agh, agl, wfh + (3*i + 2) * 4096, wfl + (3*i + 2) * 4096,
            bb[i], nullptr, houth[i], houtl[i], NNODES, actOut[i]);
        if (i == 1) {
            bn_stats<<<512, 256>>>(h2h, h2l);
            bn_apply_leaky<<<4096, 256>>>(h2h, h2l, gam, bet);
        }
        hinh = houth[i];
        hinl = houtl[i];
    }

    classifier<<<(NNODES + 255) / 256, 256>>>(h1h, h1l, wc, bc, out);
}

// round 5
// speedup vs baseline: 1.1684x; 1.1684x over previous
#include <cuda_runtime.h>
#include <cuda_bf16.h>

// ---------------------------------------------------------------------------
// GraphSAGE(pool) x3 + BN + classifier — GB300 sm_103a
// Round 5: HMMA bf16-split GEMM; A and W both pre-split bf16 in gmem, staged
// via cp.async with k-chunk double buffering; smem ldmatrix for A and W
// (round-3 compute structure); launch_bounds(256,1) to avoid spills.
// ---------------------------------------------------------------------------

#define NNODES 100000
#define NEDGES 1000000
#define F      128
#define NCLS   16
#define NEG_SLOPE 0.01f
#define BN_EPS    1e-5f
#define TILE_M 128
#define NTILES ((NNODES + TILE_M - 1) / TILE_M)   // 782

#define ACT_NONE  0
#define ACT_RELU  1
#define ACT_LEAKY 2

typedef unsigned int u32;
typedef unsigned long long u64;

// ------------------------------ scratch -----------------------------------
__device__ __align__(256) float g_hp [(size_t)NNODES * F];   // fp32 agg-gather input
__device__ __align__(256) __nv_bfloat16 g_xh [(size_t)NNODES * F];
__device__ __align__(256) __nv_bfloat16 g_xl [(size_t)NNODES * F];
__device__ __align__(256) __nv_bfloat16 g_agh[(size_t)NNODES * F];
__device__ __align__(256) __nv_bfloat16 g_agl[(size_t)NNODES * F];
__device__ __align__(256) __nv_bfloat16 g_h1h[(size_t)NNODES * F];
__device__ __align__(256) __nv_bfloat16 g_h1l[(size_t)NNODES * F];
__device__ __align__(256) __nv_bfloat16 g_h2h[(size_t)NNODES * F];
__device__ __align__(256) __nv_bfloat16 g_h2l[(size_t)NNODES * F];
__device__ __align__(256) __nv_bfloat16 g_wth[9 * F * F];   // transposed [N,K] hi
__device__ __align__(256) __nv_bfloat16 g_wtl[9 * F * F];   // transposed [N,K] lo
__device__ int   g_deg[NNODES];
__device__ int   g_rowptr[NNODES + 1];
__device__ int   g_cursor[NNODES];
__device__ int   g_col[NEDGES];
__device__ float g_sums[2 * F];

// ------------------------------ helpers -----------------------------------
__device__ __forceinline__ u32 smem_u32(const void* p) {
    u32 a;
    asm("{ .reg .u64 t; cvta.to.shared.u64 t, %1; cvt.u32.u64 %0, t; }"
        : "=r"(a) : "l"(p));
    return a;
}

__device__ __forceinline__ float bfh(u32 w) { return __uint_as_float(w & 0xffff0000u); }
__device__ __forceinline__ float bfl(u32 w) { return __uint_as_float(w << 16); }

__device__ __forceinline__ void split_pair(float a, float b, u32& oh, u32& ol) {
    __nv_bfloat16 ha = __float2bfloat16(a), hb = __float2bfloat16(b);
    __nv_bfloat16 la = __float2bfloat16(a - __bfloat162float(ha));
    __nv_bfloat16 lb = __float2bfloat16(b - __bfloat162float(hb));
    oh = (u32)__bfloat16_as_ushort(ha) | ((u32)__bfloat16_as_ushort(hb) << 16);
    ol = (u32)__bfloat16_as_ushort(la) | ((u32)__bfloat16_as_ushort(lb) << 16);
}

__device__ __forceinline__ void ldm_x4(u32 addr, u32& r0, u32& r1, u32& r2, u32& r3) {
    asm volatile("ldmatrix.sync.aligned.m8n8.x4.shared.b16 {%0,%1,%2,%3}, [%4];"
                 : "=r"(r0), "=r"(r1), "=r"(r2), "=r"(r3) : "r"(addr));
}

__device__ __forceinline__ void mma16816(float* c, const u32* a, u32 b0, u32 b1) {
    asm volatile("mma.sync.aligned.m16n8k16.row.col.f32.bf16.bf16.f32 "
                 "{%0,%1,%2,%3}, {%4,%5,%6,%7}, {%8,%9}, {%0,%1,%2,%3};"
                 : "+f"(c[0]), "+f"(c[1]), "+f"(c[2]), "+f"(c[3])
                 : "r"(a[0]), "r"(a[1]), "r"(a[2]), "r"(a[3]), "r"(b0), "r"(b1));
}

__device__ __forceinline__ void cp16(u32 dst, const void* src, int sz) {
    asm volatile("cp.async.cg.shared.global [%0], [%1], 16, %2;"
                 :: "r"(dst), "l"(__cvta_generic_to_global(src)), "r"(sz) : "memory");
}

// ------------------------------ CSR build ---------------------------------
__global__ void zero_prep() {
    int i = blockIdx.x * blockDim.x + threadIdx.x;
    if (i < NNODES) g_deg[i] = 0;
    if (i < 2 * F)  g_sums[i] = 0.f;
}

__global__ void deg_kernel(const int* __restrict__ dst) {
    int i = blockIdx.x * blockDim.x + threadIdx.x;
    if (i < NEDGES) atomicAdd(&g_deg[dst[i]], 1);
}

__global__ void scan_kernel() {
    __shared__ int sh[1024];
    int t = threadIdx.x;
    const int chunk = (NNODES + 1023) / 1024;
    int beg = t * chunk; if (beg > NNODES) beg = NNODES;
    int end = beg + chunk; if (end > NNODES) end = NNODES;
    int s = 0;
    for (int i = beg; i < end; i++) s += g_deg[i];
    sh[t] = s;
    __syncthreads();
    for (int off = 1; off < 1024; off <<= 1) {
        int v = (t >= off) ? sh[t - off] : 0;
        __syncthreads();
        sh[t] += v;
        __syncthreads();
    }
    int run = (t == 0) ? 0 : sh[t - 1];
    for (int i = beg; i < end; i++) {
        g_rowptr[i] = run;
        g_cursor[i] = run;
        run += g_deg[i];
    }
    if (t == 1023) g_rowptr[NNODES] = sh[1023];
}

__global__ void fill_kernel(const int* __restrict__ src,
                            const int* __restrict__ dst) {
    int i = blockIdx.x * blockDim.x + threadIdx.x;
    if (i < NEDGES) {
        int p = atomicAdd(&g_cursor[dst[i]], 1);
        g_col[p] = src[i];
    }
}

// ------------------------------ packing -----------------------------------
__global__ void pack_x(const float* __restrict__ x,
                       __nv_bfloat16* __restrict__ xh,
                       __nv_bfloat16* __restrict__ xl) {
    size_t i = (size_t)blockIdx.x * blockDim.x + threadIdx.x;
    size_t total = (size_t)NNODES * F / 4;
    if (i >= total) return;
    float4 v = ((const float4*)x)[i];
    uint2 oh, ol;
    split_pair(v.x, v.y, oh.x, ol.x);
    split_pair(v.z, v.w, oh.y, ol.y);
    ((uint2*)xh)[i] = oh;
    ((uint2*)xl)[i] = ol;
}

// out[n*128+k] = split(W[k*128+n])   (transposed, bf16 hi/lo)
__global__ void pack_w(const float* __restrict__ W,
                       __nv_bfloat16* __restrict__ oh,
                       __nv_bfloat16* __restrict__ ol) {
    int e = blockIdx.x * blockDim.x + threadIdx.x;
    if (e >= F * F) return;
    int n = e >> 7, k = e & 127;
    float v = W[k * F + n];
    __nv_bfloat16 h = __float2bfloat16(v);
    __nv_bfloat16 l = __float2bfloat16(v - __bfloat162float(h));
    oh[e] = h;
    ol[e] = l;
}

// ---------------------- segment-max aggregation ----------------------------
// fp32 gather (hp), split bf16 output. hp >= 0 post-relu, so 0-init max
// equals where(deg>0, segment_max, 0) exactly.
__global__ void __launch_bounds__(256) agg_max(const float* __restrict__ hp,
                                               __nv_bfloat16* __restrict__ Oh,
                                               __nv_bfloat16* __restrict__ Ol) {
    int node = (blockIdx.x * blockDim.x + threadIdx.x) >> 5;
    int lane = threadIdx.x & 31;
    if (node >= NNODES) return;
    int beg = g_rowptr[node];
    int end = g_rowptr[node + 1];
    float4 acc = make_float4(0.f, 0.f, 0.f, 0.f);
    const float4* hp4 = (const float4*)hp;
    for (int base = beg; base < end; base += 32) {
        int m = end - base; if (m > 32) m = 32;
        int idx = (lane < m) ? g_col[base + lane] : 0;
        for (int j = 0; j < m; j++) {
            int s = __shfl_sync(0xffffffffu, idx, j);
            float4 v = hp4[(size_t)s * 32 + lane];
            acc.x = fmaxf(acc.x, v.x);
            acc.y = fmaxf(acc.y, v.y);
            acc.z = fmaxf(acc.z, v.z);
            acc.w = fmaxf(acc.w, v.w);
        }
    }
    uint2 oh, ol;
    split_pair(acc.x, acc.y, oh.x, ol.x);
    split_pair(acc.z, acc.w, oh.y, ol.y);
    ((uint2*)(Oh + (size_t)node * F))[lane] = oh;
    ((uint2*)(Ol + (size_t)node * F))[lane] = ol;
}

// ------------------------------- HMMA GEMM ---------------------------------
// C[nRows,128] = A@W (+ A2@W2) + bias (+act).
// A, W pre-split bf16 in gmem; cp.async staging; k-chunk double buffering.
#define RSTRIDE 272
#define TBYTES (128 * RSTRIDE)   // 34816

// stage one 64-col k-chunk (granules j in [c*8, c*8+8)) of a 128x128 bf16 tile
__device__ __forceinline__ void stage_chunk(const __nv_bfloat16* __restrict__ src,
                                            u32 dstbase, int row0, int nRows,
                                            int tid, int c) {
    #pragma unroll
    for (int i = 0; i < 4; i++) {
        int g = tid + i * 256;           // 0..1023
        int r = g >> 3;                  // row 0..127
        int j = (g & 7) + c * 8;         // granule 16B
        int gr = row0 + r;
        int ok = (gr < nRows);
        cp16(dstbase + (u32)r * RSTRIDE + (u32)j * 16,
             src + ((size_t)(ok ? gr : 0) * F + (j << 3)), ok ? 16 : 0);
    }
}

__global__ void __launch_bounds__(256, 1) mma_gemm(
    const __nv_bfloat16* __restrict__ Ah, const __nv_bfloat16* __restrict__ Al,
    const __nv_bfloat16* __restrict__ Wh, const __nv_bfloat16* __restrict__ Wl,
    const __nv_bfloat16* __restrict__ A2h, const __nv_bfloat16* __restrict__ A2l,
    const __nv_bfloat16* __restrict__ W2h, const __nv_bfloat16* __restrict__ W2l,
    const float* __restrict__ bias,
    float* __restrict__ Cf,                                          // fp32 out (or null)
    __nv_bfloat16* __restrict__ Ch, __nv_bfloat16* __restrict__ Cl,  // split out
    int nRows, int act)
{
    extern __shared__ char dyn[];
    __shared__ float s_bias[F];
    u32 base = smem_u32(dyn);
    const u32 AH = base, AL = base + TBYTES, WH = base + 2 * TBYTES, WL = base + 3 * TBYTES;

    int tid  = threadIdx.x;
    int wid  = tid >> 5;
    int lane = tid & 31;
    int warp_m = wid & 3;
    int warp_n = wid >> 2;
    int row0 = blockIdx.x * TILE_M;

    if (tid < F) s_bias[tid] = bias[tid];

    float acc[2][8][4];
    #pragma unroll
    for (int mt = 0; mt < 2; mt++)
        #pragma unroll
        for (int nt = 0; nt < 8; nt++)
            #pragma unroll
            for (int q = 0; q < 4; q++) acc[mt][nt][q] = 0.f;

    u32 a_row  = (u32)(warp_m * 32) + (lane & 15);
    u32 a_koff = (u32)(lane >> 4) * 16;
    u32 b_row  = (u32)(warp_n * 64) + ((lane >> 4) & 1) * 8 + (lane & 7);
    u32 b_koff = (u32)((lane >> 3) & 1) * 16;

    int nPass = (A2h != nullptr) ? 2 : 1;
    for (int pass = 0; pass < nPass; pass++) {
        const __nv_bfloat16* ah_g = pass ? A2h : Ah;
        const __nv_bfloat16* al_g = pass ? A2l : Al;
        const __nv_bfloat16* wh_g = pass ? W2h : Wh;
        const __nv_bfloat16* wl_g = pass ? W2l : Wl;

        if (pass) __syncthreads();   // previous tiles fully consumed

        // chunk 0 then chunk 1, separate commit groups
        stage_chunk(ah_g, AH, row0, nRows, tid, 0);
        stage_chunk(al_g, AL, row0, nRows, tid, 0);
        stage_chunk(wh_g, WH, 0, F, tid, 0);
        stage_chunk(wl_g, WL, 0, F, tid, 0);
        asm volatile("cp.async.commit_group;" ::: "memory");
        stage_chunk(ah_g, AH, row0, nRows, tid, 1);
        stage_chunk(al_g, AL, row0, nRows, tid, 1);
        stage_chunk(wh_g, WH, 0, F, tid, 1);
        stage_chunk(wl_g, WL, 0, F, tid, 1);
        asm volatile("cp.async.commit_group;" ::: "memory");

        asm volatile("cp.async.wait_group 1;" ::: "memory");
        __syncthreads();

        #pragma unroll
        for (int chunk = 0; chunk < 2; chunk++) {
            if (chunk == 1) {
                asm volatile("cp.async.wait_group 0;" ::: "memory");
                __syncthreads();
            }
            #pragma unroll
            for (int kk = 0; kk < 4; kk++) {
                int k16 = chunk * 4 + kk;
                u32 kbase = (u32)k16 * 32;
                u32 ah[2][4], al[2][4];
                #pragma unroll
                for (int mt = 0; mt < 2; mt++) {
                    u32 off = (a_row + mt * 16) * RSTRIDE + kbase + a_koff;
                    ldm_x4(AH + off, ah[mt][0], ah[mt][1], ah[mt][2], ah[mt][3]);
                    ldm_x4(AL + off, al[mt][0], al[mt][1], al[mt][2], al[mt][3]);
                }
                u32 bh[8][2], bl[8][2];
                #pragma unroll
                for (int nt2 = 0; nt2 < 4; nt2++) {
                    u32 off = (b_row + nt2 * 16) * RSTRIDE + kbase + b_koff;
                    ldm_x4(WH + off, bh[2*nt2][0], bh[2*nt2][1], bh[2*nt2+1][0], bh[2*nt2+1][1]);
                    ldm_x4(WL + off, bl[2*nt2][0], bl[2*nt2][1], bl[2*nt2+1][0], bl[2*nt2+1][1]);
                }
                #pragma unroll
                for (int mt = 0; mt < 2; mt++)
                    #pragma unroll
                    for (int nt = 0; nt < 8; nt++) {
                        mma16816(acc[mt][nt], ah[mt], bh[nt][0], bh[nt][1]);
                        mma16816(acc[mt][nt], ah[mt], bl[nt][0], bl[nt][1]);
                        mma16816(acc[mt][nt], al[mt], bh[nt][0], bh[nt][1]);
                    }
            }
        }
    }

    // epilogue
    int rbase = row0 + warp_m * 32 + (lane >> 2);
    int cbase = warp_n * 64 + (lane & 3) * 2;
    #pragma unroll
    for (int mt = 0; mt < 2; mt++) {
        #pragma unroll
        for (int half = 0; half < 2; half++) {
            int grow = rbase + mt * 16 + half * 8;
            if (grow >= nRows) continue;
            #pragma unroll
            for (int nt = 0; nt < 8; nt++) {
                int col = cbase + nt * 8;
                float v0 = acc[mt][nt][2 * half]     + s_bias[col];
                float v1 = acc[mt][nt][2 * half + 1] + s_bias[col + 1];
                if (act == ACT_RELU) {
                    v0 = fmaxf(v0, 0.f); v1 = fmaxf(v1, 0.f);
                } else if (act == ACT_LEAKY) {
                    v0 = (v0 > 0.f) ? v0 : v0 * NEG_SLOPE;
                    v1 = (v1 > 0.f) ? v1 : v1 * NEG_SLOPE;
                }
                if (Cf) {
                    *(float2*)&Cf[(size_t)grow * F + col] = make_float2(v0, v1);
                } else {
                    u32 oh, ol;
                    split_pair(v0, v1, oh, ol);
                    ((u32*)Ch)[((size_t)grow * F + col) >> 1] = oh;
                    ((u32*)Cl)[((size_t)grow * F + col) >> 1] = ol;
                }
            }
        }
    }
}

// ------------------------------ BatchNorm ----------------------------------
__global__ void bn_stats(const __nv_bfloat16* __restrict__ Xh,
                         const __nv_bfloat16* __restrict__ Xl) {
    int cp   = threadIdx.x & 63;
    int half = threadIdx.x >> 6;
    float s0 = 0.f, s1 = 0.f, q0 = 0.f, q1 = 0.f;
    for (int r = blockIdx.x * 4 + half; r < NNODES; r += gridDim.x * 4) {
        u32 h = ((const u32*)(Xh + (size_t)r * F))[cp];
        u32 l = ((const u32*)(Xl + (size_t)r * F))[cp];
        float v0 = bfl(h) + bfl(l);
        float v1 = bfh(h) + bfh(l);
        s0 += v0; q0 += v0 * v0;
        s1 += v1; q1 += v1 * v1;
    }
    __shared__ float sh0[256], sh1[256], sq0[256], sq1[256];
    sh0[threadIdx.x] = s0; sh1[threadIdx.x] = s1;
    sq0[threadIdx.x] = q0; sq1[threadIdx.x] = q1;
    __syncthreads();
    if (half == 0) {
        s0 = sh0[cp] + sh0[cp + 64] + sh0[cp + 128] + sh0[cp + 192];
        s1 = sh1[cp] + sh1[cp + 64] + sh1[cp + 128] + sh1[cp + 192];
        q0 = sq0[cp] + sq0[cp + 64] + sq0[cp + 128] + sq0[cp + 192];
        q1 = sq1[cp] + sq1[cp + 64] + sq1[cp + 128] + sq1[cp + 192];
        atomicAdd(&g_sums[2 * cp],         s0);
        atomicAdd(&g_sums[2 * cp + 1],     s1);
        atomicAdd(&g_sums[F + 2 * cp],     q0);
        atomicAdd(&g_sums[F + 2 * cp + 1], q1);
    }
}

__global__ void bn_apply_leaky(__nv_bfloat16* __restrict__ Xh,
                               __nv_bfloat16* __restrict__ Xl,
                               const float* __restrict__ gamma,
                               const float* __restrict__ beta) {
    __shared__ float scale[F], shift[F];
    if (threadIdx.x < F) {
        float mu  = g_sums[threadIdx.x] * (1.f / NNODES);
        float var = g_sums[F + threadIdx.x] * (1.f / NNODES) - mu * mu;
        float sc  = rsqrtf(var + BN_EPS) * gamma[threadIdx.x];
        scale[threadIdx.x] = sc;
        shift[threadIdx.x] = beta[threadIdx.x] - mu * sc;
    }
    __syncthreads();
    size_t total = (size_t)NNODES * 16;
    for (size_t i = blockIdx.x * blockDim.x + threadIdx.x; i < total;
         i += (size_t)gridDim.x * blockDim.x) {
        int c = (int)(i & 15) * 8;
        uint4 hv = ((uint4*)Xh)[i];
        uint4 lv = ((uint4*)Xl)[i];
        u32 ha[4] = {hv.x, hv.y, hv.z, hv.w};
        u32 la[4] = {lv.x, lv.y, lv.z, lv.w};
        u32 oh[4], ol[4];
        #pragma unroll
        for (int w = 0; w < 4; w++) {
            float v0 = bfl(ha[w]) + bfl(la[w]);
            float v1 = bfh(ha[w]) + bfh(la[w]);
            v0 = v0 * scale[c + 2*w]     + shift[c + 2*w];
            v1 = v1 * scale[c + 2*w + 1] + shift[c + 2*w + 1];
            v0 = (v0 > 0.f) ? v0 : v0 * NEG_SLOPE;
            v1 = (v1 > 0.f) ? v1 : v1 * NEG_SLOPE;
            split_pair(v0, v1, oh[w], ol[w]);
        }
        ((uint4*)Xh)[i] = make_uint4(oh[0], oh[1], oh[2], oh[3]);
        ((uint4*)Xl)[i] = make_uint4(ol[0], ol[1], ol[2], ol[3]);
    }
}

// ------------------------------ classifier ---------------------------------
__global__ void classifier(const __nv_bfloat16* __restrict__ Hh,
                           const __nv_bfloat16* __restrict__ Hl,
                           const float* __restrict__ wc,
                           const float* __restrict__ bc,
                           float* __restrict__ out) {
    __shared__ float w[F * NCLS];
    __shared__ float b[NCLS];
    for (int i = threadIdx.x; i < F * NCLS; i += blockDim.x) w[i] = wc[i];
    if (threadIdx.x < NCLS) b[threadIdx.x] = bc[threadIdx.x];
    __syncthreads();
    int r = blockIdx.x * blockDim.x + threadIdx.x;
    if (r >= NNODES) return;
    float acc[NCLS];
    #pragma unroll
    for (int j = 0; j < NCLS; j++) acc[j] = 0.f;
    for (int k = 0; k < F; k += 8) {
        uint4 hv = *(const uint4*)(Hh + (size_t)r * F + k);
        uint4 lv = *(const uint4*)(Hl + (size_t)r * F + k);
        u32 ha[4] = {hv.x, hv.y, hv.z, hv.w};
        u32 la[4] = {lv.x, lv.y, lv.z, lv.w};
        #pragma unroll
        for (int t = 0; t < 4; t++) {
            float f0 = bfl(ha[t]) + bfl(la[t]);
            float f1 = bfh(ha[t]) + bfh(la[t]);
            #pragma unroll
            for (int j = 0; j < NCLS; j++)
                acc[j] += f0 * w[(k + 2*t) * NCLS + j] + f1 * w[(k + 2*t + 1) * NCLS + j];
        }
    }
    #pragma unroll
    for (int j = 0; j < NCLS; j++)
        out[(size_t)r * NCLS + j] = acc[j] + b[j];
}

// ------------------------------ launch -------------------------------------
extern "C" void kernel_launch(void* const* d_in, const int* in_sizes, int n_in,
                              void* d_out, int out_size) {
    const float* x   = (const float*)d_in[0];
    const int*   src = (const int*)  d_in[1];
    const int*   dst = (const int*)  d_in[2];
    const float* wp[3] = { (const float*)d_in[3], (const float*)d_in[8],  (const float*)d_in[13] };
    const float* bp[3] = { (const float*)d_in[4], (const float*)d_in[9],  (const float*)d_in[14] };
    const float* ws[3] = { (const float*)d_in[5], (const float*)d_in[10], (const float*)d_in[15] };
    const float* wn[3] = { (const float*)d_in[6], (const float*)d_in[11], (const float*)d_in[16] };
    const float* bb[3] = { (const float*)d_in[7], (const float*)d_in[12], (const float*)d_in[17] };
    const float* gam = (const float*)d_in[18];
    const float* bet = (const float*)d_in[19];
    const float* wc  = (const float*)d_in[20];
    const float* bc  = (const float*)d_in[21];
    float* out = (float*)d_out;

    float* hp;
    __nv_bfloat16 *xh, *xl, *agh, *agl, *h1h, *h1l, *h2h, *h2l, *wth, *wtl;
    cudaGetSymbolAddress((void**)&hp,  g_hp);
    cudaGetSymbolAddress((void**)&xh,  g_xh);
    cudaGetSymbolAddress((void**)&xl,  g_xl);
    cudaGetSymbolAddress((void**)&agh, g_agh);
    cudaGetSymbolAddress((void**)&agl, g_agl);
    cudaGetSymbolAddress((void**)&h1h, g_h1h);
    cudaGetSymbolAddress((void**)&h1l, g_h1l);
    cudaGetSymbolAddress((void**)&h2h, g_h2h);
    cudaGetSymbolAddress((void**)&h2l, g_h2l);
    cudaGetSymbolAddress((void**)&wth, g_wth);
    cudaGetSymbolAddress((void**)&wtl, g_wtl);

    const int SMEM_DYN = 4 * TBYTES;   // 139264
    cudaFuncSetAttribute(mma_gemm, cudaFuncAttributeMaxDynamicSharedMemorySize, SMEM_DYN);

    const int edgeGrid = (NEDGES + 255) / 256;
    const int aggGrid  = (NNODES * 32 + 255) / 256;
    const int FF = F * F;

    // CSR build
    zero_prep<<<(NNODES + 255) / 256, 256>>>();
    deg_kernel<<<edgeGrid, 256>>>(dst);
    scan_kernel<<<1, 1024>>>();
    fill_kernel<<<edgeGrid, 256>>>(src, dst);

    // pack inputs + weights (slot 3i=wp, 3i+1=ws, 3i+2=wn)
    pack_x<<<(NNODES * F / 4 + 255) / 256, 256>>>(x, xh, xl);
    for (int i = 0; i < 3; i++) {
        pack_w<<<64, 256>>>(wp[i], wth + (3*i)     * FF, wtl + (3*i)     * FF);
        pack_w<<<64, 256>>>(ws[i], wth + (3*i + 1) * FF, wtl + (3*i + 1) * FF);
        pack_w<<<64, 256>>>(wn[i], wth + (3*i + 2) * FF, wtl + (3*i + 2) * FF);
    }

    const __nv_bfloat16 *hinh = xh, *hinl = xl;
    __nv_bfloat16* houth[3] = { h1h, h2h, h1h };
    __nv_bfloat16* houtl[3] = { h1l, h2l, h1l };
    int actOut[3] = { ACT_LEAKY, ACT_NONE, ACT_NONE };

    for (int i = 0; i < 3; i++) {
        // hp = relu(h @ wp + bp)   (fp32 out for agg gather)
        mma_gemm<<<NTILES, 256, SMEM_DYN>>>(
            hinh, hinl, wth + (3*i) * FF, wtl + (3*i) * FF,
            nullptr, nullptr, nullptr, nullptr,
            bp[i], hp, nullptr, nullptr, NNODES, ACT_RELU);
        // agg = segment_max(hp[src] -> dst)  (split bf16 out)
        agg_max<<<aggGrid, 256>>>(hp, agh, agl);
        // h' = h @ ws + agg @ wn + b
        mma_gemm<<<NTILES, 256, SMEM_DYN>>>(
            hinh, hinl, wth + (3*i + 1) * FF, wtl + (3*i + 1) * FF,
            agh, agl, wth + (3*i + 2) * FF, wtl + (3*i + 2) * FF,
            bb[i], nullptr, houth[i], houtl[i], NNODES, actOut[i]);
        if (i == 1) {
            bn_stats<<<512, 256>>>(h2h, h2l);
            bn_apply_leaky<<<4096, 256>>>(h2h, h2l, gam, bet);
        }
        hinh = houth[i];
        hinl = houtl[i];
    }

    classifier<<<(NNODES + 255) / 256, 256>>>(h1h, h1l, wc, bc, out);
}

// round 6
// speedup vs baseline: 1.5356x; 1.3143x over previous
#include <cuda_runtime.h>
#include <cuda_fp16.h>

// ---------------------------------------------------------------------------
// GraphSAGE(pool) x3 + BN + classifier — GB300 sm_103a
// Round 6: activations plain fp16, weights split fp16 hi/lo -> 2 MMA terms
// per GEMM (A*Wh + A*Wl). Halves activation traffic everywhere; agg uses
// exact hmax2 on fp16. MMA-issue-bound model says -1/3 GEMM time.
// ---------------------------------------------------------------------------

#define NNODES 100000
#define NEDGES 1000000
#define F      128
#define NCLS   16
#define NEG_SLOPE 0.01f
#define BN_EPS    1e-5f
#define TILE_M 128
#define NTILES ((NNODES + TILE_M - 1) / TILE_M)   // 782

#define ACT_NONE  0
#define ACT_RELU  1
#define ACT_LEAKY 2

typedef unsigned int u32;
typedef unsigned long long u64;

// ------------------------------ scratch -----------------------------------
__device__ __align__(256) __half g_x16[(size_t)NNODES * F];
__device__ __align__(256) __half g_hp [(size_t)NNODES * F];
__device__ __align__(256) __half g_ag [(size_t)NNODES * F];
__device__ __align__(256) __half g_h1 [(size_t)NNODES * F];
__device__ __align__(256) __half g_h2 [(size_t)NNODES * F];
__device__ __align__(256) __half g_wth[9 * F * F];   // transposed [N,K] hi
__device__ __align__(256) __half g_wtl[9 * F * F];   // transposed [N,K] lo
__device__ int   g_deg[NNODES];
__device__ int   g_rowptr[NNODES + 1];
__device__ int   g_cursor[NNODES];
__device__ int   g_col[NEDGES];
__device__ float g_sums[2 * F];

// ------------------------------ helpers -----------------------------------
__device__ __forceinline__ u32 smem_u32(const void* p) {
    u32 a;
    asm("{ .reg .u64 t; cvta.to.shared.u64 t, %1; cvt.u32.u64 %0, t; }"
        : "=r"(a) : "l"(p));
    return a;
}

__device__ __forceinline__ void ldm_x4(u32 addr, u32& r0, u32& r1, u32& r2, u32& r3) {
    asm volatile("ldmatrix.sync.aligned.m8n8.x4.shared.b16 {%0,%1,%2,%3}, [%4];"
                 : "=r"(r0), "=r"(r1), "=r"(r2), "=r"(r3) : "r"(addr));
}

__device__ __forceinline__ void mma16816(float* c, const u32* a, u32 b0, u32 b1) {
    asm volatile("mma.sync.aligned.m16n8k16.row.col.f32.f16.f16.f32 "
                 "{%0,%1,%2,%3}, {%4,%5,%6,%7}, {%8,%9}, {%0,%1,%2,%3};"
                 : "+f"(c[0]), "+f"(c[1]), "+f"(c[2]), "+f"(c[3])
                 : "r"(a[0]), "r"(a[1]), "r"(a[2]), "r"(a[3]), "r"(b0), "r"(b1));
}

__device__ __forceinline__ void cp16(u32 dst, const void* src, int sz) {
    asm volatile("cp.async.cg.shared.global [%0], [%1], 16, %2;"
                 :: "r"(dst), "l"(__cvta_generic_to_global(src)), "r"(sz) : "memory");
}

__device__ __forceinline__ u32 pack_half2(float a, float b) {
    __half2 h = __floats2half2_rn(a, b);
    return *(u32*)&h;
}

// ------------------------------ CSR build ---------------------------------
__global__ void zero_prep() {
    int i = blockIdx.x * blockDim.x + threadIdx.x;
    if (i < NNODES) g_deg[i] = 0;
    if (i < 2 * F)  g_sums[i] = 0.f;
}

__global__ void deg_kernel(const int* __restrict__ dst) {
    int i = blockIdx.x * blockDim.x + threadIdx.x;
    if (i < NEDGES) atomicAdd(&g_deg[dst[i]], 1);
}

__global__ void scan_kernel() {
    __shared__ int sh[1024];
    int t = threadIdx.x;
    const int chunk = (NNODES + 1023) / 1024;
    int beg = t * chunk; if (beg > NNODES) beg = NNODES;
    int end = beg + chunk; if (end > NNODES) end = NNODES;
    int s = 0;
    for (int i = beg; i < end; i++) s += g_deg[i];
    sh[t] = s;
    __syncthreads();
    for (int off = 1; off < 1024; off <<= 1) {
        int v = (t >= off) ? sh[t - off] : 0;
        __syncthreads();
        sh[t] += v;
        __syncthreads();
    }
    int run = (t == 0) ? 0 : sh[t - 1];
    for (int i = beg; i < end; i++) {
        g_rowptr[i] = run;
        g_cursor[i] = run;
        run += g_deg[i];
    }
    if (t == 1023) g_rowptr[NNODES] = sh[1023];
}

__global__ void fill_kernel(const int* __restrict__ src,
                            const int* __restrict__ dst) {
    int i = blockIdx.x * blockDim.x + threadIdx.x;
    if (i < NEDGES) {
        int p = atomicAdd(&g_cursor[dst[i]], 1);
        g_col[p] = src[i];
    }
}

// ------------------------------ packing -----------------------------------
__global__ void pack_x(const float* __restrict__ x, __half* __restrict__ xo) {
    size_t i = (size_t)blockIdx.x * blockDim.x + threadIdx.x;
    size_t total = (size_t)NNODES * F / 4;
    if (i >= total) return;
    float4 v = ((const float4*)x)[i];
    uint2 o;
    o.x = pack_half2(v.x, v.y);
    o.y = pack_half2(v.z, v.w);
    ((uint2*)xo)[i] = o;
}

// all 9 weights in one launch; out[n*128+k] = split(W[k*128+n]) fp16 hi/lo
struct W9 { const float* p[9]; };
__global__ void pack_w_all(W9 w9, __half* __restrict__ oh, __half* __restrict__ ol) {
    int e = blockIdx.x * blockDim.x + threadIdx.x;
    if (e >= F * F) return;
    const float* W = w9.p[blockIdx.y];
    size_t off = (size_t)blockIdx.y * F * F;
    int n = e >> 7, k = e & 127;
    float v = W[k * F + n];
    __half h = __float2half_rn(v);
    __half l = __float2half_rn(v - __half2float(h));
    oh[off + e] = h;
    ol[off + e] = l;
}

// ---------------------- segment-max aggregation ----------------------------
// fp16 gather; exact hmax2 (selection). hp >= 0 post-relu, 0-init valid.
__global__ void __launch_bounds__(256) agg_max(const __half* __restrict__ hp,
                                               __half* __restrict__ O) {
    int node = (blockIdx.x * blockDim.x + threadIdx.x) >> 5;
    int lane = threadIdx.x & 31;
    if (node >= NNODES) return;
    int beg = g_rowptr[node];
    int end = g_rowptr[node + 1];
    __half2 a0 = __floats2half2_rn(0.f, 0.f), a1 = a0;
    const uint2* hp2 = (const uint2*)hp;          // 32 lanes x 8B per row
    for (int base = beg; base < end; base += 32) {
        int m = end - base; if (m > 32) m = 32;
        int idx = (lane < m) ? g_col[base + lane] : 0;
        for (int j = 0; j < m; j++) {
            int s = __shfl_sync(0xffffffffu, idx, j);
            uint2 v = hp2[(size_t)s * 32 + lane];
            a0 = __hmax2(a0, *(__half2*)&v.x);
            a1 = __hmax2(a1, *(__half2*)&v.y);
        }
    }
    uint2 o;
    o.x = *(u32*)&a0;
    o.y = *(u32*)&a1;
    ((uint2*)(O + (size_t)node * F))[lane] = o;
}

// ------------------------------- HMMA GEMM ---------------------------------
// C[nRows,128] = A@(Wh+Wl) (+ A2@(W2h+W2l)) + bias (+act). A fp16, W pre-split.
#define RSTRIDE 272
#define TBYTES (128 * RSTRIDE)   // 34816

__device__ __forceinline__ void stage_chunk(const __half* __restrict__ src,
                                            u32 dstbase, int row0, int nRows,
                                            int tid, int c) {
    #pragma unroll
    for (int i = 0; i < 4; i++) {
        int g = tid + i * 256;           // 0..1023
        int r = g >> 3;                  // row 0..127
        int j = (g & 7) + c * 8;         // 16B granule
        int gr = row0 + r;
        int ok = (gr < nRows);
        cp16(dstbase + (u32)r * RSTRIDE + (u32)j * 16,
             src + ((size_t)(ok ? gr : 0) * F + (j << 3)), ok ? 16 : 0);
    }
}

__global__ void __launch_bounds__(256, 1) mma_gemm(
    const __half* __restrict__ A,
    const __half* __restrict__ Wh, const __half* __restrict__ Wl,
    const __half* __restrict__ A2,
    const __half* __restrict__ W2h, const __half* __restrict__ W2l,
    const float* __restrict__ bias,
    __half* __restrict__ C,
    int nRows, int act)
{
    extern __shared__ char dyn[];
    __shared__ float s_bias[F];
    u32 base = smem_u32(dyn);
    const u32 AT = base, WH = base + TBYTES, WL = base + 2 * TBYTES;

    int tid  = threadIdx.x;
    int wid  = tid >> 5;
    int lane = tid & 31;
    int warp_m = wid & 3;
    int warp_n = wid >> 2;
    int row0 = blockIdx.x * TILE_M;

    if (tid < F) s_bias[tid] = bias[tid];

    float acc[2][8][4];
    #pragma unroll
    for (int mt = 0; mt < 2; mt++)
        #pragma unroll
        for (int nt = 0; nt < 8; nt++)
            #pragma unroll
            for (int q = 0; q < 4; q++) acc[mt][nt][q] = 0.f;

    u32 a_row  = (u32)(warp_m * 32) + (lane & 15);
    u32 a_koff = (u32)(lane >> 4) * 16;
    u32 b_row  = (u32)(warp_n * 64) + ((lane >> 4) & 1) * 8 + (lane & 7);
    u32 b_koff = (u32)((lane >> 3) & 1) * 16;

    int nPass = (A2 != nullptr) ? 2 : 1;
    for (int pass = 0; pass < nPass; pass++) {
        const __half* a_g  = pass ? A2 : A;
        const __half* wh_g = pass ? W2h : Wh;
        const __half* wl_g = pass ? W2l : Wl;

        if (pass) __syncthreads();

        stage_chunk(a_g,  AT, row0, nRows, tid, 0);
        stage_chunk(wh_g, WH, 0, F, tid, 0);
        stage_chunk(wl_g, WL, 0, F, tid, 0);
        asm volatile("cp.async.commit_group;" ::: "memory");
        stage_chunk(a_g,  AT, row0, nRows, tid, 1);
        stage_chunk(wh_g, WH, 0, F, tid, 1);
        stage_chunk(wl_g, WL, 0, F, tid, 1);
        asm volatile("cp.async.commit_group;" ::: "memory");

        asm volatile("cp.async.wait_group 1;" ::: "memory");
        __syncthreads();

        #pragma unroll
        for (int chunk = 0; chunk < 2; chunk++) {
            if (chunk == 1) {
                asm volatile("cp.async.wait_group 0;" ::: "memory");
                __syncthreads();
            }
            #pragma unroll
            for (int kk = 0; kk < 4; kk++) {
                int k16 = chunk * 4 + kk;
                u32 kbase = (u32)k16 * 32;
                u32 ah[2][4];
                #pragma unroll
                for (int mt = 0; mt < 2; mt++) {
                    u32 off = (a_row + mt * 16) * RSTRIDE + kbase + a_koff;
                    ldm_x4(AT + off, ah[mt][0], ah[mt][1], ah[mt][2], ah[mt][3]);
                }
                u32 bh[8][2], bl[8][2];
                #pragma unroll
                for (int nt2 = 0; nt2 < 4; nt2++) {
                    u32 off = (b_row + nt2 * 16) * RSTRIDE + kbase + b_koff;
                    ldm_x4(WH + off, bh[2*nt2][0], bh[2*nt2][1], bh[2*nt2+1][0], bh[2*nt2+1][1]);
                    ldm_x4(WL + off, bl[2*nt2][0], bl[2*nt2][1], bl[2*nt2+1][0], bl[2*nt2+1][1]);
                }
                #pragma unroll
                for (int mt = 0; mt < 2; mt++)
                    #pragma unroll
                    for (int nt = 0; nt < 8; nt++) {
                        mma16816(acc[mt][nt], ah[mt], bh[nt][0], bh[nt][1]);
                        mma16816(acc[mt][nt], ah[mt], bl[nt][0], bl[nt][1]);
                    }
            }
        }
    }

    // epilogue: bias + act, fp16 store
    int rbase = row0 + warp_m * 32 + (lane >> 2);
    int cbase = warp_n * 64 + (lane & 3) * 2;
    #pragma unroll
    for (int mt = 0; mt < 2; mt++) {
        #pragma unroll
        for (int half = 0; half < 2; half++) {
            int grow = rbase + mt * 16 + half * 8;
            if (grow >= nRows) continue;
            #pragma unroll
            for (int nt = 0; nt < 8; nt++) {
                int col = cbase + nt * 8;
                float v0 = acc[mt][nt][2 * half]     + s_bias[col];
                float v1 = acc[mt][nt][2 * half + 1] + s_bias[col + 1];
                if (act == ACT_RELU) {
                    v0 = fmaxf(v0, 0.f); v1 = fmaxf(v1, 0.f);
                } else if (act == ACT_LEAKY) {
                    v0 = (v0 > 0.f) ? v0 : v0 * NEG_SLOPE;
                    v1 = (v1 > 0.f) ? v1 : v1 * NEG_SLOPE;
                }
                ((u32*)C)[((size_t)grow * F + col) >> 1] = pack_half2(v0, v1);
            }
        }
    }
}

// ------------------------------ BatchNorm ----------------------------------
__global__ void bn_stats(const __half* __restrict__ X) {
    int cp   = threadIdx.x & 63;    // u32 index within row (cols 2cp, 2cp+1)
    int half = threadIdx.x >> 6;    // 0..3
    float s0 = 0.f, s1 = 0.f, q0 = 0.f, q1 = 0.f;
    for (int r = blockIdx.x * 4 + half; r < NNODES; r += gridDim.x * 4) {
        u32 h = ((const u32*)(X + (size_t)r * F))[cp];
        float2 v = __half22float2(*(__half2*)&h);
        s0 += v.x; q0 += v.x * v.x;
        s1 += v.y; q1 += v.y * v.y;
    }
    __shared__ float sh0[256], sh1[256], sq0[256], sq1[256];
    sh0[threadIdx.x] = s0; sh1[threadIdx.x] = s1;
    sq0[threadIdx.x] = q0; sq1[threadIdx.x] = q1;
    __syncthreads();
    if (half == 0) {
        s0 = sh0[cp] + sh0[cp + 64] + sh0[cp + 128] + sh0[cp + 192];
        s1 = sh1[cp] + sh1[cp + 64] + sh1[cp + 128] + sh1[cp + 192];
        q0 = sq0[cp] + sq0[cp + 64] + sq0[cp + 128] + sq0[cp + 192];
        q1 = sq1[cp] + sq1[cp + 64] + sq1[cp + 128] + sq1[cp + 192];
        atomicAdd(&g_sums[2 * cp],         s0);
        atomicAdd(&g_sums[2 * cp + 1],     s1);
        atomicAdd(&g_sums[F + 2 * cp],     q0);
        atomicAdd(&g_sums[F + 2 * cp + 1], q1);
    }
}

__global__ void bn_apply_leaky(__half* __restrict__ X,
                               const float* __restrict__ gamma,
                               const float* __restrict__ beta) {
    __shared__ float scale[F], shift[F];
    if (threadIdx.x < F) {
        float mu  = g_sums[threadIdx.x] * (1.f / NNODES);
        float var = g_sums[F + threadIdx.x] * (1.f / NNODES) - mu * mu;
        float sc  = rsqrtf(var + BN_EPS) * gamma[threadIdx.x];
        scale[threadIdx.x] = sc;
        shift[threadIdx.x] = beta[threadIdx.x] - mu * sc;
    }
    __syncthreads();
    size_t total = (size_t)NNODES * 16;   // groups of 8 fp16 (16B)
    for (size_t i = blockIdx.x * blockDim.x + threadIdx.x; i < total;
         i += (size_t)gridDim.x * blockDim.x) {
        int c = (int)(i & 15) * 8;
        uint4 hv = ((uint4*)X)[i];
        u32 a[4] = {hv.x, hv.y, hv.z, hv.w};
        #pragma unroll
        for (int w = 0; w < 4; w++) {
            float2 v = __half22float2(*(__half2*)&a[w]);
            v.x = v.x * scale[c + 2*w]     + shift[c + 2*w];
            v.y = v.y * scale[c + 2*w + 1] + shift[c + 2*w + 1];
            v.x = (v.x > 0.f) ? v.x : v.x * NEG_SLOPE;
            v.y = (v.y > 0.f) ? v.y : v.y * NEG_SLOPE;
            a[w] = pack_half2(v.x, v.y);
        }
        ((uint4*)X)[i] = make_uint4(a[0], a[1], a[2], a[3]);
    }
}

// ------------------------------ classifier ---------------------------------
__global__ void classifier(const __half* __restrict__ H,
                           const float* __restrict__ wc,
                           const float* __restrict__ bc,
                           float* __restrict__ out) {
    __shared__ float w[F * NCLS];
    __shared__ float b[NCLS];
    for (int i = threadIdx.x; i < F * NCLS; i += blockDim.x) w[i] = wc[i];
    if (threadIdx.x < NCLS) b[threadIdx.x] = bc[threadIdx.x];
    __syncthreads();
    int r = blockIdx.x * blockDim.x + threadIdx.x;
    if (r >= NNODES) return;
    float acc[NCLS];
    #pragma unroll
    for (int j = 0; j < NCLS; j++) acc[j] = 0.f;
    for (int k = 0; k < F; k += 8) {
        uint4 hv = *(const uint4*)(H + (size_t)r * F + k);
        u32 a[4] = {hv.x, hv.y, hv.z, hv.w};
        #pragma unroll
        for (int t = 0; t < 4; t++) {
            float2 v = __half22float2(*(__half2*)&a[t]);
            #pragma unroll
            for (int j = 0; j < NCLS; j++)
                acc[j] += v.x * w[(k + 2*t) * NCLS + j] + v.y * w[(k + 2*t + 1) * NCLS + j];
        }
    }
    #pragma unroll
    for (int j = 0; j < NCLS; j++)
        out[(size_t)r * NCLS + j] = acc[j] + b[j];
}

// ------------------------------ launch -------------------------------------
extern "C" void kernel_launch(void* const* d_in, const int* in_sizes, int n_in,
                              void* d_out, int out_size) {
    const float* x   = (const float*)d_in[0];
    const int*   src = (const int*)  d_in[1];
    const int*   dst = (const int*)  d_in[2];
    const float* wp[3] = { (const float*)d_in[3], (const float*)d_in[8],  (const float*)d_in[13] };
    const float* bp[3] = { (const float*)d_in[4], (const float*)d_in[9],  (const float*)d_in[14] };
    const float* ws[3] = { (const float*)d_in[5], (const float*)d_in[10], (const float*)d_in[15] };
    const float* wn[3] = { (const float*)d_in[6], (const float*)d_in[11], (const float*)d_in[16] };
    const float* bb[3] = { (const float*)d_in[7], (const float*)d_in[12], (const float*)d_in[17] };
    const float* gam = (const float*)d_in[18];
    const float* bet = (const float*)d_in[19];
    const float* wc  = (const float*)d_in[20];
    const float* bc  = (const float*)d_in[21];
    float* out = (float*)d_out;

    __half *x16, *hp, *ag, *h1, *h2, *wth, *wtl;
    cudaGetSymbolAddress((void**)&x16, g_x16);
    cudaGetSymbolAddress((void**)&hp,  g_hp);
    cudaGetSymbolAddress((void**)&ag,  g_ag);
    cudaGetSymbolAddress((void**)&h1,  g_h1);
    cudaGetSymbolAddress((void**)&h2,  g_h2);
    cudaGetSymbolAddress((void**)&wth, g_wth);
    cudaGetSymbolAddress((void**)&wtl, g_wtl);

    const int SMEM_DYN = 3 * TBYTES;   // 104448
    cudaFuncSetAttribute(mma_gemm, cudaFuncAttributeMaxDynamicSharedMemorySize, SMEM_DYN);

    const int edgeGrid = (NEDGES + 255) / 256;
    const int aggGrid  = (NNODES * 32 + 255) / 256;
    const int FF = F * F;

    // CSR build
    zero_prep<<<(NNODES + 255) / 256, 256>>>();
    deg_kernel<<<edgeGrid, 256>>>(dst);
    scan_kernel<<<1, 1024>>>();
    fill_kernel<<<edgeGrid, 256>>>(src, dst);

    // pack inputs + weights (slot 3i=wp, 3i+1=ws, 3i+2=wn)
    pack_x<<<(NNODES * F / 4 + 255) / 256, 256>>>(x, x16);
    W9 w9;
    for (int i = 0; i < 3; i++) {
        w9.p[3*i]     = wp[i];
        w9.p[3*i + 1] = ws[i];
        w9.p[3*i + 2] = wn[i];
    }
    pack_w_all<<<dim3(64, 9), 256>>>(w9, wth, wtl);

    const __half* hin = x16;
    __half* hout[3] = { h1, h2, h1 };
    int actOut[3] = { ACT_LEAKY, ACT_NONE, ACT_NONE };

    for (int i = 0; i < 3; i++) {
        // hp = relu(h @ wp + bp)
        mma_gemm<<<NTILES, 256, SMEM_DYN>>>(
            hin, wth + (3*i) * FF, wtl + (3*i) * FF,
            nullptr, nullptr, nullptr,
            bp[i], hp, NNODES, ACT_RELU);
        // agg = segment_max(hp[src] -> dst)
        agg_max<<<aggGrid, 256>>>(hp, ag);
        // h' = h @ ws + agg @ wn + b
        mma_gemm<<<NTILES, 256, SMEM_DYN>>>(
            hin, wth + (3*i + 1) * FF, wtl + (3*i + 1) * FF,
            ag, wth + (3*i + 2) * FF, wtl + (3*i + 2) * FF,
            bb[i], hout[i], NNODES, actOut[i]);
        if (i == 1) {
            bn_stats<<<512, 256>>>(h2);
            bn_apply_leaky<<<4096, 256>>>(h2, gam, bet);
        }
        hin = hout[i];
    }

    classifier<<<(NNODES + 255) / 256, 256>>>(h1, wc, bc, out);
}

// round 7
// speedup vs baseline: 1.6337x; 1.0639x over previous
#include <cuda_runtime.h>
#include <cuda_fp16.h>

// ---------------------------------------------------------------------------
// GraphSAGE(pool) x3 + BN + classifier — GB300 sm_103a
// Round 7: persistent HMMA GEMM (grid = #SMs). W resident in smem, staged
// once per CTA; A double-buffered across tiles via cp.async groups.
// Numerics: activations fp16, weights fp16 hi/lo split (2 MMA terms).
// ---------------------------------------------------------------------------

#define NNODES 100000
#define NEDGES 1000000
#define F      128
#define NCLS   16
#define NEG_SLOPE 0.01f
#define BN_EPS    1e-5f
#define TILE_M 128
#define NTILES ((NNODES + TILE_M - 1) / TILE_M)   // 782
#define GRIDP  152                                 // GB300 SM count

#define ACT_NONE  0
#define ACT_RELU  1
#define ACT_LEAKY 2

typedef unsigned int u32;
typedef unsigned long long u64;

// ------------------------------ scratch -----------------------------------
__device__ __align__(256) __half g_x16[(size_t)NNODES * F];
__device__ __align__(256) __half g_hp [(size_t)NNODES * F];
__device__ __align__(256) __half g_ag [(size_t)NNODES * F];
__device__ __align__(256) __half g_h1 [(size_t)NNODES * F];
__device__ __align__(256) __half g_h2 [(size_t)NNODES * F];
__device__ __align__(256) __half g_wth[9 * F * F];   // transposed [N,K] hi
__device__ __align__(256) __half g_wtl[9 * F * F];   // transposed [N,K] lo
__device__ int   g_deg[NNODES];
__device__ int   g_rowptr[NNODES + 1];
__device__ int   g_cursor[NNODES];
__device__ int   g_col[NEDGES];
__device__ float g_sums[2 * F];

// ------------------------------ helpers -----------------------------------
__device__ __forceinline__ u32 smem_u32(const void* p) {
    u32 a;
    asm("{ .reg .u64 t; cvta.to.shared.u64 t, %1; cvt.u32.u64 %0, t; }"
        : "=r"(a) : "l"(p));
    return a;
}

__device__ __forceinline__ void ldm_x4(u32 addr, u32& r0, u32& r1, u32& r2, u32& r3) {
    asm volatile("ldmatrix.sync.aligned.m8n8.x4.shared.b16 {%0,%1,%2,%3}, [%4];"
                 : "=r"(r0), "=r"(r1), "=r"(r2), "=r"(r3) : "r"(addr));
}

__device__ __forceinline__ void mma16816(float* c, const u32* a, u32 b0, u32 b1) {
    asm volatile("mma.sync.aligned.m16n8k16.row.col.f32.f16.f16.f32 "
                 "{%0,%1,%2,%3}, {%4,%5,%6,%7}, {%8,%9}, {%0,%1,%2,%3};"
                 : "+f"(c[0]), "+f"(c[1]), "+f"(c[2]), "+f"(c[3])
                 : "r"(a[0]), "r"(a[1]), "r"(a[2]), "r"(a[3]), "r"(b0), "r"(b1));
}

__device__ __forceinline__ void cp16(u32 dst, const void* src, int sz) {
    asm volatile("cp.async.cg.shared.global [%0], [%1], 16, %2;"
                 :: "r"(dst), "l"(__cvta_generic_to_global(src)), "r"(sz) : "memory");
}
#define CP_COMMIT() asm volatile("cp.async.commit_group;" ::: "memory")
#define CP_WAIT1()  asm volatile("cp.async.wait_group 1;" ::: "memory")

__device__ __forceinline__ u32 pack_half2(float a, float b) {
    __half2 h = __floats2half2_rn(a, b);
    return *(u32*)&h;
}

// ------------------------------ CSR build ---------------------------------
__global__ void zero_prep() {
    int i = blockIdx.x * blockDim.x + threadIdx.x;
    if (i < NNODES) g_deg[i] = 0;
    if (i < 2 * F)  g_sums[i] = 0.f;
}

__global__ void deg_kernel(const int* __restrict__ dst) {
    int i = blockIdx.x * blockDim.x + threadIdx.x;
    if (i < NEDGES) atomicAdd(&g_deg[dst[i]], 1);
}

__global__ void scan_kernel() {
    __shared__ int sh[1024];
    int t = threadIdx.x;
    const int chunk = (NNODES + 1023) / 1024;
    int beg = t * chunk; if (beg > NNODES) beg = NNODES;
    int end = beg + chunk; if (end > NNODES) end = NNODES;
    int s = 0;
    for (int i = beg; i < end; i++) s += g_deg[i];
    sh[t] = s;
    __syncthreads();
    for (int off = 1; off < 1024; off <<= 1) {
        int v = (t >= off) ? sh[t - off] : 0;
        __syncthreads();
        sh[t] += v;
        __syncthreads();
    }
    int run = (t == 0) ? 0 : sh[t - 1];
    for (int i = beg; i < end; i++) {
        g_rowptr[i] = run;
        g_cursor[i] = run;
        run += g_deg[i];
    }
    if (t == 1023) g_rowptr[NNODES] = sh[1023];
}

__global__ void fill_kernel(const int* __restrict__ src,
                            const int* __restrict__ dst) {
    int i = blockIdx.x * blockDim.x + threadIdx.x;
    if (i < NEDGES) {
        int p = atomicAdd(&g_cursor[dst[i]], 1);
        g_col[p] = src[i];
    }
}

// ------------------------------ packing -----------------------------------
__global__ void pack_x(const float* __restrict__ x, __half* __restrict__ xo) {
    size_t i = (size_t)blockIdx.x * blockDim.x + threadIdx.x;
    size_t total = (size_t)NNODES * F / 4;
    if (i >= total) return;
    float4 v = ((const float4*)x)[i];
    uint2 o;
    o.x = pack_half2(v.x, v.y);
    o.y = pack_half2(v.z, v.w);
    ((uint2*)xo)[i] = o;
}

struct W9 { const float* p[9]; };
__global__ void pack_w_all(W9 w9, __half* __restrict__ oh, __half* __restrict__ ol) {
    int e = blockIdx.x * blockDim.x + threadIdx.x;
    if (e >= F * F) return;
    const float* W = w9.p[blockIdx.y];
    size_t off = (size_t)blockIdx.y * F * F;
    int n = e >> 7, k = e & 127;
    float v = W[k * F + n];
    __half h = __float2half_rn(v);
    __half l = __float2half_rn(v - __half2float(h));
    oh[off + e] = h;
    ol[off + e] = l;
}

// ---------------------- segment-max aggregation ----------------------------
__global__ void __launch_bounds__(256) agg_max(const __half* __restrict__ hp,
                                               __half* __restrict__ O) {
    int node = (blockIdx.x * blockDim.x + threadIdx.x) >> 5;
    int lane = threadIdx.x & 31;
    if (node >= NNODES) return;
    int beg = g_rowptr[node];
    int end = g_rowptr[node + 1];
    __half2 a0 = __floats2half2_rn(0.f, 0.f), a1 = a0;
    const uint2* hp2 = (const uint2*)hp;
    for (int base = beg; base < end; base += 32) {
        int m = end - base; if (m > 32) m = 32;
        int idx = (lane < m) ? g_col[base + lane] : 0;
        for (int j = 0; j < m; j++) {
            int s = __shfl_sync(0xffffffffu, idx, j);
            uint2 v = hp2[(size_t)s * 32 + lane];
            a0 = __hmax2(a0, *(__half2*)&v.x);
            a1 = __hmax2(a1, *(__half2*)&v.y);
        }
    }
    uint2 o;
    o.x = *(u32*)&a0;
    o.y = *(u32*)&a1;
    ((uint2*)(O + (size_t)node * F))[lane] = o;
}

// ------------------------- persistent HMMA GEMM ----------------------------
#define RSTRIDE 272
#define TBYTES (128 * RSTRIDE)   // 34816

// stage a full 128x128 fp16 tile (rows row0..row0+127, zero-fill OOB)
__device__ __forceinline__ void stage_tile(const __half* __restrict__ src,
                                           u32 dstbase, int row0, int nRows, int tid) {
    #pragma unroll
    for (int i = 0; i < 8; i++) {
        int g = tid + i * 256;           // 0..2047
        int r = g >> 4;                  // row 0..127
        int j = g & 15;                  // 16B granule
        int gr = row0 + r;
        int ok = (gr < nRows);
        cp16(dstbase + (u32)r * RSTRIDE + (u32)j * 16,
             src + ((size_t)(ok ? gr : 0) * F + (j << 3)), ok ? 16 : 0);
    }
}

__device__ __forceinline__ void compute_tile(u32 AT, u32 WHb, u32 WLb,
                                             float acc[2][8][4],
                                             u32 a_row, u32 a_koff,
                                             u32 b_row, u32 b_koff) {
    #pragma unroll
    for (int k16 = 0; k16 < 8; k16++) {
        u32 kbase = (u32)k16 * 32;
        u32 ah[2][4];
        #pragma unroll
        for (int mt = 0; mt < 2; mt++) {
            u32 off = (a_row + mt * 16) * RSTRIDE + kbase + a_koff;
            ldm_x4(AT + off, ah[mt][0], ah[mt][1], ah[mt][2], ah[mt][3]);
        }
        u32 bh[8][2], bl[8][2];
        #pragma unroll
        for (int nt2 = 0; nt2 < 4; nt2++) {
            u32 off = (b_row + nt2 * 16) * RSTRIDE + kbase + b_koff;
            ldm_x4(WHb + off, bh[2*nt2][0], bh[2*nt2][1], bh[2*nt2+1][0], bh[2*nt2+1][1]);
            ldm_x4(WLb + off, bl[2*nt2][0], bl[2*nt2][1], bl[2*nt2+1][0], bl[2*nt2+1][1]);
        }
        #pragma unroll
        for (int mt = 0; mt < 2; mt++)
            #pragma unroll
            for (int nt = 0; nt < 8; nt++) {
                mma16816(acc[mt][nt], ah[mt], bh[nt][0], bh[nt][1]);
                mma16816(acc[mt][nt], ah[mt], bl[nt][0], bl[nt][1]);
            }
    }
}

__global__ void __launch_bounds__(256, 1) mma_gemm_pers(
    const __half* __restrict__ A,        // pass-1 activations
    const __half* __restrict__ A2,       // pass-2 activations (null = single)
    const __half* __restrict__ Wh, const __half* __restrict__ Wl,
    const __half* __restrict__ W2h, const __half* __restrict__ W2l,
    const float* __restrict__ bias,
    __half* __restrict__ C,
    int nRows, int act)
{
    extern __shared__ char dyn[];
    __shared__ float s_bias[F];
    u32 base = smem_u32(dyn);
    const u32 A0  = base,              A1  = base + TBYTES;
    const u32 W1H = base + 2 * TBYTES, W1L = base + 3 * TBYTES;
    const u32 W2H = base + 4 * TBYTES, W2L = base + 5 * TBYTES;

    int tid  = threadIdx.x;
    int wid  = tid >> 5;
    int lane = tid & 31;
    int warp_m = wid & 3;
    int warp_n = wid >> 2;
    bool two = (A2 != nullptr);

    if (tid < F) s_bias[tid] = bias[tid];

    u32 a_row  = (u32)(warp_m * 32) + (lane & 15);
    u32 a_koff = (u32)(lane >> 4) * 16;
    u32 b_row  = (u32)(warp_n * 64) + ((lane >> 4) & 1) * 8 + (lane & 7);
    u32 b_koff = (u32)((lane >> 3) & 1) * 16;

    // resident weights (one group)
    stage_tile(Wh, W1H, 0, F, tid);
    stage_tile(Wl, W1L, 0, F, tid);
    if (two) {
        stage_tile(W2h, W2H, 0, F, tid);
        stage_tile(W2l, W2L, 0, F, tid);
    }
    CP_COMMIT();

    int t0 = blockIdx.x;

    // prologue A staging
    if (two) {
        if (t0 < NTILES) stage_tile(A,  A0, t0 * TILE_M, nRows, tid);
        CP_COMMIT();
        if (t0 < NTILES) stage_tile(A2, A1, t0 * TILE_M, nRows, tid);
        CP_COMMIT();
    } else {
        if (t0 < NTILES) stage_tile(A, A0, t0 * TILE_M, nRows, tid);
        CP_COMMIT();
        int t1 = t0 + GRIDP;
        if (t1 < NTILES) stage_tile(A, A1, t1 * TILE_M, nRows, tid);
        CP_COMMIT();
    }

    int it = 0;
    for (int t = t0; t < NTILES; t += GRIDP, it++) {
        float acc[2][8][4];
        #pragma unroll
        for (int mt = 0; mt < 2; mt++)
            #pragma unroll
            for (int nt = 0; nt < 8; nt++)
                #pragma unroll
                for (int q = 0; q < 4; q++) acc[mt][nt][q] = 0.f;

        if (two) {
            int tn = t + GRIDP;
            // pass 1: h @ W1
            CP_WAIT1();
            __syncthreads();
            compute_tile(A0, W1H, W1L, acc, a_row, a_koff, b_row, b_koff);
            __syncthreads();
            if (tn < NTILES) stage_tile(A, A0, tn * TILE_M, nRows, tid);
            CP_COMMIT();
            // pass 2: agg @ W2
            CP_WAIT1();
            __syncthreads();
            compute_tile(A1, W2H, W2L, acc, a_row, a_koff, b_row, b_koff);
            __syncthreads();
            if (tn < NTILES) stage_tile(A2, A1, tn * TILE_M, nRows, tid);
            CP_COMMIT();
        } else {
            u32 Abuf = (it & 1) ? A1 : A0;
            int tn = t + 2 * GRIDP;
            CP_WAIT1();
            __syncthreads();
            compute_tile(Abuf, W1H, W1L, acc, a_row, a_koff, b_row, b_koff);
            __syncthreads();
            if (tn < NTILES) stage_tile(A, Abuf, tn * TILE_M, nRows, tid);
            CP_COMMIT();
        }

        // epilogue: bias + act, fp16 store
        int row0 = t * TILE_M;
        int rbase = row0 + warp_m * 32 + (lane >> 2);
        int cbase = warp_n * 64 + (lane & 3) * 2;
        #pragma unroll
        for (int mt = 0; mt < 2; mt++) {
            #pragma unroll
            for (int half = 0; half < 2; half++) {
                int grow = rbase + mt * 16 + half * 8;
                if (grow >= nRows) continue;
                #pragma unroll
                for (int nt = 0; nt < 8; nt++) {
                    int col = cbase + nt * 8;
                    float v0 = acc[mt][nt][2 * half]     + s_bias[col];
                    float v1 = acc[mt][nt][2 * half + 1] + s_bias[col + 1];
                    if (act == ACT_RELU) {
                        v0 = fmaxf(v0, 0.f); v1 = fmaxf(v1, 0.f);
                    } else if (act == ACT_LEAKY) {
                        v0 = (v0 > 0.f) ? v0 : v0 * NEG_SLOPE;
                        v1 = (v1 > 0.f) ? v1 : v1 * NEG_SLOPE;
                    }
                    ((u32*)C)[((size_t)grow * F + col) >> 1] = pack_half2(v0, v1);
                }
            }
        }
    }
}

// ------------------------------ BatchNorm ----------------------------------
__global__ void bn_stats(const __half* __restrict__ X) {
    int cp   = threadIdx.x & 63;
    int half = threadIdx.x >> 6;
    float s0 = 0.f, s1 = 0.f, q0 = 0.f, q1 = 0.f;
    for (int r = blockIdx.x * 4 + half; r < NNODES; r += gridDim.x * 4) {
        u32 h = ((const u32*)(X + (size_t)r * F))[cp];
        float2 v = __half22float2(*(__half2*)&h);
        s0 += v.x; q0 += v.x * v.x;
        s1 += v.y; q1 += v.y * v.y;
    }
    __shared__ float sh0[256], sh1[256], sq0[256], sq1[256];
    sh0[threadIdx.x] = s0; sh1[threadIdx.x] = s1;
    sq0[threadIdx.x] = q0; sq1[threadIdx.x] = q1;
    __syncthreads();
    if (half == 0) {
        s0 = sh0[cp] + sh0[cp + 64] + sh0[cp + 128] + sh0[cp + 192];
        s1 = sh1[cp] + sh1[cp + 64] + sh1[cp + 128] + sh1[cp + 192];
        q0 = sq0[cp] + sq0[cp + 64] + sq0[cp + 128] + sq0[cp + 192];
        q1 = sq1[cp] + sq1[cp + 64] + sq1[cp + 128] + sq1[cp + 192];
        atomicAdd(&g_sums[2 * cp],         s0);
        atomicAdd(&g_sums[2 * cp + 1],     s1);
        atomicAdd(&g_sums[F + 2 * cp],     q0);
        atomicAdd(&g_sums[F + 2 * cp + 1], q1);
    }
}

__global__ void bn_apply_leaky(__half* __restrict__ X,
                               const float* __restrict__ gamma,
                               const float* __restrict__ beta) {
    __shared__ float scale[F], shift[F];
    if (threadIdx.x < F) {
        float mu  = g_sums[threadIdx.x] * (1.f / NNODES);
        float var = g_sums[F + threadIdx.x] * (1.f / NNODES) - mu * mu;
        float sc  = rsqrtf(var + BN_EPS) * gamma[threadIdx.x];
        scale[threadIdx.x] = sc;
        shift[threadIdx.x] = beta[threadIdx.x] - mu * sc;
    }
    __syncthreads();
    size_t total = (size_t)NNODES * 16;
    for (size_t i = blockIdx.x * blockDim.x + threadIdx.x; i < total;
         i += (size_t)gridDim.x * blockDim.x) {
        int c = (int)(i & 15) * 8;
        uint4 hv = ((uint4*)X)[i];
        u32 a[4] = {hv.x, hv.y, hv.z, hv.w};
        #pragma unroll
        for (int w = 0; w < 4; w++) {
            float2 v = __half22float2(*(__half2*)&a[w]);
            v.x = v.x * scale[c + 2*w]     + shift[c + 2*w];
            v.y = v.y * scale[c + 2*w + 1] + shift[c + 2*w + 1];
            v.x = (v.x > 0.f) ? v.x : v.x * NEG_SLOPE;
            v.y = (v.y > 0.f) ? v.y : v.y * NEG_SLOPE;
            a[w] = pack_half2(v.x, v.y);
        }
        ((uint4*)X)[i] = make_uint4(a[0], a[1], a[2], a[3]);
    }
}

// ------------------------------ classifier ---------------------------------
__global__ void classifier(const __half* __restrict__ H,
                           const float* __restrict__ wc,
                           const float* __restrict__ bc,
                           float* __restrict__ out) {
    __shared__ float w[F * NCLS];
    __shared__ float b[NCLS];
    for (int i = threadIdx.x; i < F * NCLS; i += blockDim.x) w[i] = wc[i];
    if (threadIdx.x < NCLS) b[threadIdx.x] = bc[threadIdx.x];
    __syncthreads();
    int r = blockIdx.x * blockDim.x + threadIdx.x;
    if (r >= NNODES) return;
    float acc[NCLS];
    #pragma unroll
    for (int j = 0; j < NCLS; j++) acc[j] = 0.f;
    for (int k = 0; k < F; k += 8) {
        uint4 hv = *(const uint4*)(H + (size_t)r * F + k);
        u32 a[4] = {hv.x, hv.y, hv.z, hv.w};
        #pragma unroll
        for (int t = 0; t < 4; t++) {
            float2 v = __half22float2(*(__half2*)&a[t]);
            #pragma unroll
            for (int j = 0; j < NCLS; j++)
                acc[j] += v.x * w[(k + 2*t) * NCLS + j] + v.y * w[(k + 2*t + 1) * NCLS + j];
        }
    }
    #pragma unroll
    for (int j = 0; j < NCLS; j++)
        out[(size_t)r * NCLS + j] = acc[j] + b[j];
}

// ------------------------------ launch -------------------------------------
extern "C" void kernel_launch(void* const* d_in, const int* in_sizes, int n_in,
                              void* d_out, int out_size) {
    const float* x   = (const float*)d_in[0];
    const int*   src = (const int*)  d_in[1];
    const int*   dst = (const int*)  d_in[2];
    const float* wp[3] = { (const float*)d_in[3], (const float*)d_in[8],  (const float*)d_in[13] };
    const float* bp[3] = { (const float*)d_in[4], (const float*)d_in[9],  (const float*)d_in[14] };
    const float* ws[3] = { (const float*)d_in[5], (const float*)d_in[10], (const float*)d_in[15] };
    const float* wn[3] = { (const float*)d_in[6], (const float*)d_in[11], (const float*)d_in[16] };
    const float* bb[3] = { (const float*)d_in[7], (const float*)d_in[12], (const float*)d_in[17] };
    const float* gam = (const float*)d_in[18];
    const float* bet = (const float*)d_in[19];
    const float* wc  = (const float*)d_in[20];
    const float* bc  = (const float*)d_in[21];
    float* out = (float*)d_out;

    __half *x16, *hp, *ag, *h1, *h2, *wth, *wtl;
    cudaGetSymbolAddress((void**)&x16, g_x16);
    cudaGetSymbolAddress((void**)&hp,  g_hp);
    cudaGetSymbolAddress((void**)&ag,  g_ag);
    cudaGetSymbolAddress((void**)&h1,  g_h1);
    cudaGetSymbolAddress((void**)&h2,  g_h2);
    cudaGetSymbolAddress((void**)&wth, g_wth);
    cudaGetSymbolAddress((void**)&wtl, g_wtl);

    const int SMEM_DYN = 6 * TBYTES;   // 208896
    cudaFuncSetAttribute(mma_gemm_pers, cudaFuncAttributeMaxDynamicSharedMemorySize, SMEM_DYN);

    const int edgeGrid = (NEDGES + 255) / 256;
    const int aggGrid  = (NNODES * 32 + 255) / 256;
    const int FF = F * F;

    // CSR build
    zero_prep<<<(NNODES + 255) / 256, 256>>>();
    deg_kernel<<<edgeGrid, 256>>>(dst);
    scan_kernel<<<1, 1024>>>();
    fill_kernel<<<edgeGrid, 256>>>(src, dst);

    // pack inputs + weights (slot 3i=wp, 3i+1=ws, 3i+2=wn)
    pack_x<<<(NNODES * F / 4 + 255) / 256, 256>>>(x, x16);
    W9 w9;
    for (int i = 0; i < 3; i++) {
        w9.p[3*i]     = wp[i];
        w9.p[3*i + 1] = ws[i];
        w9.p[3*i + 2] = wn[i];
    }
    pack_w_all<<<dim3(64, 9), 256>>>(w9, wth, wtl);

    const __half* hin = x16;
    __half* hout[3] = { h1, h2, h1 };
    int actOut[3] = { ACT_LEAKY, ACT_NONE, ACT_NONE };

    for (int i = 0; i < 3; i++) {
        // hp = relu(h @ wp + bp)
        mma_gemm_pers<<<GRIDP, 256, SMEM_DYN>>>(
            hin, nullptr,
            wth + (3*i) * FF, wtl + (3*i) * FF,
            nullptr, nullptr,
            bp[i], hp, NNODES, ACT_RELU);
        // agg = segment_max(hp[src] -> dst)
        agg_max<<<aggGrid, 256>>>(hp, ag);
        // h' = h @ ws + agg @ wn + b
        mma_gemm_pers<<<GRIDP, 256, SMEM_DYN>>>(
            hin, ag,
            wth + (3*i + 1) * FF, wtl + (3*i + 1) * FF,
            wth + (3*i + 2) * FF, wtl + (3*i + 2) * FF,
            bb[i], hout[i], NNODES, actOut[i]);
        if (i == 1) {
            bn_stats<<<512, 256>>>(h2);
            bn_apply_leaky<<<4096, 256>>>(h2, gam, bet);
        }
        hin = hout[i];
    }

    classifier<<<(NNODES + 255) / 256, 256>>>(h1, wc, bc, out);
}